// round 12
// baseline (speedup 1.0000x reference)
#include <cuda_runtime.h>

// MFELoss: softmax over C=4, masked squared-error reduction to a scalar.
// HBM-bound streaming reduction: 128 MiB preds (fp32) + 32 MiB target (int32).
// R12: latency-bound fix — 8 rows/thread/iter (10 front-batched 16B loads),
// others_idx template specialization (3 exps/row, no selects), rcp.approx.
// One exact wave: 152 SMs x 5 CTAs at <=51 regs.

#define NBLK 760    // 152 x 5
#define NTHR 256

// Per-block partials: [0]=fne_sum, [1]=fpe_sum, [2]=fne_count
static __device__ float g_part[NBLK][3];
static __device__ unsigned int g_ticket = 0;   // reset by last block each launch

__device__ __forceinline__ float rcp_fast(float x) {
    float r;
    asm("rcp.approx.f32 %0, %1;" : "=f"(r) : "f"(x));
    return r;
}

// OI known at compile time: p_o = 1 / (1 + sum_{j != OI} exp(r_j - r_OI))
// fne_i = (1-p_o)^2 (rows where target==OI), fpe_i = p_o^2 (otherwise).
template <int OI>
__device__ __forceinline__ void accum_row_t(float4 r, int t,
                                            float& fne, float& fpe, float& cnt) {
    float v0 = r.x, v1 = r.y, v2 = r.z, v3 = r.w;
    float ro = (OI == 0) ? v0 : (OI == 1) ? v1 : (OI == 2) ? v2 : v3;
    float s = 1.0f;
    if (OI != 0) s += __expf(v0 - ro);
    if (OI != 1) s += __expf(v1 - ro);
    if (OI != 2) s += __expf(v2 - ro);
    if (OI != 3) s += __expf(v3 - ro);
    float po = rcp_fast(s);
    float d  = 1.0f - po;
    if (t == OI) { fne += d * d; cnt += 1.0f; }
    else         { fpe += po * po; }
}

template <int OI>
__device__ __forceinline__ void reduce_loop(const float4* __restrict__ preds,
                                            const int4*   __restrict__ tgt4,
                                            int n_oct,
                                            float& fne, float& fpe, float& cnt) {
    const int stride = gridDim.x * blockDim.x;
    for (int i = blockIdx.x * blockDim.x + threadIdx.x; i < n_oct; i += stride) {
        // 10 independent 16B loads front-batched: 8 preds rows + 2 target quads.
        const float4* p = preds + 8 * i;
        float4 r0 = p[0];
        float4 r1 = p[1];
        float4 r2 = p[2];
        float4 r3 = p[3];
        float4 r4 = p[4];
        float4 r5 = p[5];
        float4 r6 = p[6];
        float4 r7 = p[7];
        int4   ta = tgt4[2 * i + 0];
        int4   tb = tgt4[2 * i + 1];
        accum_row_t<OI>(r0, ta.x, fne, fpe, cnt);
        accum_row_t<OI>(r1, ta.y, fne, fpe, cnt);
        accum_row_t<OI>(r2, ta.z, fne, fpe, cnt);
        accum_row_t<OI>(r3, ta.w, fne, fpe, cnt);
        accum_row_t<OI>(r4, tb.x, fne, fpe, cnt);
        accum_row_t<OI>(r5, tb.y, fne, fpe, cnt);
        accum_row_t<OI>(r6, tb.z, fne, fpe, cnt);
        accum_row_t<OI>(r7, tb.w, fne, fpe, cnt);
    }
}

__global__ void __launch_bounds__(NTHR, 5)
mfe_fused_kernel(const float4* __restrict__ preds,   // [B] rows of 4 floats
                 const int4*   __restrict__ tgt4,    // [B/4] quads of int32
                 const int*    __restrict__ oi_ptr,
                 int n_oct,                          // B/8
                 float n_total,                      // B
                 float* __restrict__ out)
{
    const int oi = *oi_ptr;   // runtime-uniform; dispatch once
    float fne = 0.0f, fpe = 0.0f, cnt = 0.0f;

    switch (oi) {
        case 0:  reduce_loop<0>(preds, tgt4, n_oct, fne, fpe, cnt); break;
        case 1:  reduce_loop<1>(preds, tgt4, n_oct, fne, fpe, cnt); break;
        case 2:  reduce_loop<2>(preds, tgt4, n_oct, fne, fpe, cnt); break;
        default: reduce_loop<3>(preds, tgt4, n_oct, fne, fpe, cnt); break;
    }

    // ---- intra-block reduce ----
    #pragma unroll
    for (int off = 16; off > 0; off >>= 1) {
        fne += __shfl_down_sync(0xFFFFFFFFu, fne, off);
        fpe += __shfl_down_sync(0xFFFFFFFFu, fpe, off);
        cnt += __shfl_down_sync(0xFFFFFFFFu, cnt, off);
    }
    __shared__ float s_fne[NTHR / 32];
    __shared__ float s_fpe[NTHR / 32];
    __shared__ float s_cnt[NTHR / 32];
    int lane = threadIdx.x & 31;
    int wid  = threadIdx.x >> 5;
    if (lane == 0) { s_fne[wid] = fne; s_fpe[wid] = fpe; s_cnt[wid] = cnt; }
    __syncthreads();
    if (threadIdx.x < 32) {
        float f = (lane < NTHR / 32) ? s_fne[lane] : 0.0f;
        float p = (lane < NTHR / 32) ? s_fpe[lane] : 0.0f;
        float c = (lane < NTHR / 32) ? s_cnt[lane] : 0.0f;
        #pragma unroll
        for (int off = 4; off > 0; off >>= 1) {
            f += __shfl_down_sync(0xFFFFFFFFu, f, off);
            p += __shfl_down_sync(0xFFFFFFFFu, p, off);
            c += __shfl_down_sync(0xFFFFFFFFu, c, off);
        }
        if (lane == 0) {
            g_part[blockIdx.x][0] = f;
            g_part[blockIdx.x][1] = p;
            g_part[blockIdx.x][2] = c;
        }
    }

    // ---- last-block finalize ----
    __shared__ bool s_is_last;
    __threadfence();                 // release: g_part visible chip-wide
    __syncthreads();
    if (threadIdx.x == 0) {
        unsigned int ticket = atomicAdd(&g_ticket, 1u);
        s_is_last = (ticket == (unsigned int)(gridDim.x - 1));
    }
    __syncthreads();
    if (!s_is_last) return;

    __threadfence();                 // acquire: see all partials

    double dfne = 0.0, dfpe = 0.0, dcnt = 0.0;
    for (int i = threadIdx.x; i < NBLK; i += NTHR) {
        dfne += (double)g_part[i][0];
        dfpe += (double)g_part[i][1];
        dcnt += (double)g_part[i][2];
    }
    #pragma unroll
    for (int off = 16; off > 0; off >>= 1) {
        dfne += __shfl_down_sync(0xFFFFFFFFu, dfne, off);
        dfpe += __shfl_down_sync(0xFFFFFFFFu, dfpe, off);
        dcnt += __shfl_down_sync(0xFFFFFFFFu, dcnt, off);
    }
    __shared__ double s_f[NTHR / 32], s_p[NTHR / 32], s_c[NTHR / 32];
    if (lane == 0) { s_f[wid] = dfne; s_p[wid] = dfpe; s_c[wid] = dcnt; }
    __syncthreads();
    if (threadIdx.x == 0) {
        double F = 0.0, P = 0.0, Cn = 0.0;
        #pragma unroll
        for (int w = 0; w < NTHR / 32; w++) { F += s_f[w]; P += s_p[w]; Cn += s_c[w]; }
        float fne_num = (float)Cn;
        float fpe_num = n_total - fne_num;
        out[0] = (float)(P / (double)fpe_num + F / (double)fne_num);
        __threadfence();
        g_ticket = 0;                // deterministic reset for next graph replay
    }
}

extern "C" void kernel_launch(void* const* d_in, const int* in_sizes, int n_in,
                              void* d_out, int out_size)
{
    const float4* preds  = (const float4*)d_in[0];
    const int4*   tgt4   = (const int4*)d_in[1];
    const int*    oi_ptr = (const int*)d_in[2];
    float*        out    = (float*)d_out;

    int n_rows = in_sizes[0] / 4;   // B
    int n_oct  = n_rows / 8;

    mfe_fused_kernel<<<NBLK, NTHR>>>(preds, tgt4, oi_ptr, n_oct, (float)n_rows, out);
}

// round 13
// speedup vs baseline: 1.1288x; 1.1288x over previous
#include <cuda_runtime.h>

// MFELoss: softmax over C=4, masked squared-error reduction to a scalar.
// HBM-bound streaming reduction: 128 MiB preds (fp32) + 32 MiB target (int32).
// R13: R11 loop shape (4 rows/thread/iter — deeper batching floods L1tex queue,
// proven in R12) at MAX occupancy: 32 regs -> 8 CTAs/SM -> 64 warps/SM,
// one exact wave of 152 x 8 = 1216 blocks.

#define NBLK 1216   // 152 SMs x 8 CTAs == one full wave at 32 regs
#define NTHR 256

// Per-block partials: [0]=fne_sum, [1]=fpe_sum, [2]=fne_count
static __device__ float g_part[NBLK][3];
static __device__ unsigned int g_ticket = 0;   // reset to 0 by last block each launch

// Simplified per-row math:
//   p_o = 1 / sum_j exp(r_j - r_o);   fne_i = (1-p_o)^2,  fpe_i = p_o^2
__device__ __forceinline__ void accum_row(float4 r, bool is_o, int oi,
                                          float& fne, float& fpe, float& cnt) {
    float ro = (oi == 0) ? r.x : (oi == 1) ? r.y : (oi == 2) ? r.z : r.w;
    float e0 = __expf(r.x - ro);
    float e1 = __expf(r.y - ro);
    float e2 = __expf(r.z - ro);
    float e3 = __expf(r.w - ro);
    float po = __frcp_rn(e0 + e1 + e2 + e3);
    float d  = 1.0f - po;
    if (is_o) { fne += d * d; cnt += 1.0f; }
    else      { fpe += po * po; }
}

__global__ void __launch_bounds__(NTHR, 8)
mfe_fused_kernel(const float4* __restrict__ preds,   // [B] rows of 4 floats
                 const int4*   __restrict__ tgt4,    // [B/4] quads of int32
                 const int*    __restrict__ oi_ptr,
                 int n_quads,                        // B/4
                 float n_total,                      // B
                 float* __restrict__ out)
{
    const int oi = *oi_ptr;
    float fne = 0.0f, fpe = 0.0f, cnt = 0.0f;

    const int stride = gridDim.x * blockDim.x;
    for (int i = blockIdx.x * blockDim.x + threadIdx.x; i < n_quads; i += stride) {
        // Front-batch 5 independent 16B loads for MLP.
        float4 r0 = preds[4 * i + 0];
        float4 r1 = preds[4 * i + 1];
        float4 r2 = preds[4 * i + 2];
        float4 r3 = preds[4 * i + 3];
        int4   t  = tgt4[i];
        accum_row(r0, t.x == oi, oi, fne, fpe, cnt);
        accum_row(r1, t.y == oi, oi, fne, fpe, cnt);
        accum_row(r2, t.z == oi, oi, fne, fpe, cnt);
        accum_row(r3, t.w == oi, oi, fne, fpe, cnt);
    }

    // ---- intra-block reduce ----
    #pragma unroll
    for (int off = 16; off > 0; off >>= 1) {
        fne += __shfl_down_sync(0xFFFFFFFFu, fne, off);
        fpe += __shfl_down_sync(0xFFFFFFFFu, fpe, off);
        cnt += __shfl_down_sync(0xFFFFFFFFu, cnt, off);
    }
    __shared__ float s_fne[NTHR / 32];
    __shared__ float s_fpe[NTHR / 32];
    __shared__ float s_cnt[NTHR / 32];
    int lane = threadIdx.x & 31;
    int wid  = threadIdx.x >> 5;
    if (lane == 0) { s_fne[wid] = fne; s_fpe[wid] = fpe; s_cnt[wid] = cnt; }
    __syncthreads();
    if (threadIdx.x < 32) {
        float f = (lane < NTHR / 32) ? s_fne[lane] : 0.0f;
        float p = (lane < NTHR / 32) ? s_fpe[lane] : 0.0f;
        float c = (lane < NTHR / 32) ? s_cnt[lane] : 0.0f;
        #pragma unroll
        for (int off = 4; off > 0; off >>= 1) {
            f += __shfl_down_sync(0xFFFFFFFFu, f, off);
            p += __shfl_down_sync(0xFFFFFFFFu, p, off);
            c += __shfl_down_sync(0xFFFFFFFFu, c, off);
        }
        if (lane == 0) {
            g_part[blockIdx.x][0] = f;
            g_part[blockIdx.x][1] = p;
            g_part[blockIdx.x][2] = c;
        }
    }

    // ---- last-block finalize ----
    __shared__ bool s_is_last;
    __threadfence();                 // release: g_part writes visible chip-wide
    __syncthreads();
    if (threadIdx.x == 0) {
        unsigned int ticket = atomicAdd(&g_ticket, 1u);
        s_is_last = (ticket == (unsigned int)(gridDim.x - 1));
    }
    __syncthreads();
    if (!s_is_last) return;

    __threadfence();                 // acquire: see all blocks' partials

    double dfne = 0.0, dfpe = 0.0, dcnt = 0.0;
    for (int i = threadIdx.x; i < NBLK; i += NTHR) {
        dfne += (double)g_part[i][0];
        dfpe += (double)g_part[i][1];
        dcnt += (double)g_part[i][2];
    }
    #pragma unroll
    for (int off = 16; off > 0; off >>= 1) {
        dfne += __shfl_down_sync(0xFFFFFFFFu, dfne, off);
        dfpe += __shfl_down_sync(0xFFFFFFFFu, dfpe, off);
        dcnt += __shfl_down_sync(0xFFFFFFFFu, dcnt, off);
    }
    __shared__ double s_f[NTHR / 32], s_p[NTHR / 32], s_c[NTHR / 32];
    if (lane == 0) { s_f[wid] = dfne; s_p[wid] = dfpe; s_c[wid] = dcnt; }
    __syncthreads();
    if (threadIdx.x == 0) {
        double F = 0.0, P = 0.0, Cn = 0.0;
        #pragma unroll
        for (int w = 0; w < NTHR / 32; w++) { F += s_f[w]; P += s_p[w]; Cn += s_c[w]; }
        float fne_num = (float)Cn;
        float fpe_num = n_total - fne_num;
        out[0] = (float)(P / (double)fpe_num + F / (double)fne_num);
        __threadfence();
        g_ticket = 0;                // deterministic reset for next graph replay
    }
}

extern "C" void kernel_launch(void* const* d_in, const int* in_sizes, int n_in,
                              void* d_out, int out_size)
{
    const float4* preds  = (const float4*)d_in[0];
    const int4*   tgt4   = (const int4*)d_in[1];
    const int*    oi_ptr = (const int*)d_in[2];
    float*        out    = (float*)d_out;

    int n_rows  = in_sizes[0] / 4;     // B
    int n_quads = n_rows / 4;

    mfe_fused_kernel<<<NBLK, NTHR>>>(preds, tgt4, oi_ptr, n_quads, (float)n_rows, out);
}

// round 14
// speedup vs baseline: 1.1791x; 1.0446x over previous
#include <cuda_runtime.h>

// MFELoss: softmax over C=4, masked squared-error reduction to a scalar.
// HBM-bound streaming reduction: 128 MiB preds (fp32) + 32 MiB target (int32).
// R14: keep R13 grid config (32 regs, 8 CTAs/SM, one wave of 1216 blocks) and
// thin the loop: others_idx template specialization (3 exps/row, no select
// chain), rcp.approx (no Newton refine), dual accumulators (shorter chains).

#define NBLK 1216   // 152 SMs x 8 CTAs == one full wave at 32 regs
#define NTHR 256

// Per-block partials: [0]=fne_sum, [1]=fpe_sum, [2]=fne_count
static __device__ float g_part[NBLK][3];
static __device__ unsigned int g_ticket = 0;   // reset to 0 by last block each launch

__device__ __forceinline__ float rcp_fast(float x) {
    float r;
    asm("rcp.approx.f32 %0, %1;" : "=f"(r) : "f"(x));
    return r;
}

// OI known at compile time:
//   p_o = 1 / (1 + sum_{j != OI} exp(r_j - r_OI))
//   fne_i = (1-p_o)^2 on rows with target==OI, fpe_i = p_o^2 otherwise.
template <int OI>
__device__ __forceinline__ void accum_row_t(float4 r, int t,
                                            float& fne, float& fpe, float& cnt) {
    float ro = (OI == 0) ? r.x : (OI == 1) ? r.y : (OI == 2) ? r.z : r.w;
    float s = 1.0f;
    if (OI != 0) s += __expf(r.x - ro);
    if (OI != 1) s += __expf(r.y - ro);
    if (OI != 2) s += __expf(r.z - ro);
    if (OI != 3) s += __expf(r.w - ro);
    float po = rcp_fast(s);
    float d  = 1.0f - po;
    if (t == OI) { fne += d * d; cnt += 1.0f; }
    else         { fpe += po * po; }
}

template <int OI>
__device__ __forceinline__ void reduce_loop(const float4* __restrict__ preds,
                                            const int4*   __restrict__ tgt4,
                                            int n_quads,
                                            float& fne, float& fpe, float& cnt) {
    // Two accumulator sets to shorten FADD dependency chains.
    float fneA = 0.0f, fpeA = 0.0f, cntA = 0.0f;
    float fneB = 0.0f, fpeB = 0.0f, cntB = 0.0f;

    const int stride = gridDim.x * blockDim.x;
    for (int i = blockIdx.x * blockDim.x + threadIdx.x; i < n_quads; i += stride) {
        // Front-batch 5 independent 16B loads (proven best depth: R12 showed
        // 10-deep floods the L1tex wavefront queue).
        float4 r0 = preds[4 * i + 0];
        float4 r1 = preds[4 * i + 1];
        float4 r2 = preds[4 * i + 2];
        float4 r3 = preds[4 * i + 3];
        int4   t  = tgt4[i];
        accum_row_t<OI>(r0, t.x, fneA, fpeA, cntA);
        accum_row_t<OI>(r1, t.y, fneB, fpeB, cntB);
        accum_row_t<OI>(r2, t.z, fneA, fpeA, cntA);
        accum_row_t<OI>(r3, t.w, fneB, fpeB, cntB);
    }
    fne = fneA + fneB;
    fpe = fpeA + fpeB;
    cnt = cntA + cntB;
}

__global__ void __launch_bounds__(NTHR, 8)
mfe_fused_kernel(const float4* __restrict__ preds,   // [B] rows of 4 floats
                 const int4*   __restrict__ tgt4,    // [B/4] quads of int32
                 const int*    __restrict__ oi_ptr,
                 int n_quads,                        // B/4
                 float n_total,                      // B
                 float* __restrict__ out)
{
    const int oi = *oi_ptr;   // runtime-uniform; dispatch once
    float fne, fpe, cnt;

    switch (oi) {
        case 0:  reduce_loop<0>(preds, tgt4, n_quads, fne, fpe, cnt); break;
        case 1:  reduce_loop<1>(preds, tgt4, n_quads, fne, fpe, cnt); break;
        case 2:  reduce_loop<2>(preds, tgt4, n_quads, fne, fpe, cnt); break;
        default: reduce_loop<3>(preds, tgt4, n_quads, fne, fpe, cnt); break;
    }

    // ---- intra-block reduce ----
    #pragma unroll
    for (int off = 16; off > 0; off >>= 1) {
        fne += __shfl_down_sync(0xFFFFFFFFu, fne, off);
        fpe += __shfl_down_sync(0xFFFFFFFFu, fpe, off);
        cnt += __shfl_down_sync(0xFFFFFFFFu, cnt, off);
    }
    __shared__ float s_fne[NTHR / 32];
    __shared__ float s_fpe[NTHR / 32];
    __shared__ float s_cnt[NTHR / 32];
    int lane = threadIdx.x & 31;
    int wid  = threadIdx.x >> 5;
    if (lane == 0) { s_fne[wid] = fne; s_fpe[wid] = fpe; s_cnt[wid] = cnt; }
    __syncthreads();
    if (threadIdx.x < 32) {
        float f = (lane < NTHR / 32) ? s_fne[lane] : 0.0f;
        float p = (lane < NTHR / 32) ? s_fpe[lane] : 0.0f;
        float c = (lane < NTHR / 32) ? s_cnt[lane] : 0.0f;
        #pragma unroll
        for (int off = 4; off > 0; off >>= 1) {
            f += __shfl_down_sync(0xFFFFFFFFu, f, off);
            p += __shfl_down_sync(0xFFFFFFFFu, p, off);
            c += __shfl_down_sync(0xFFFFFFFFu, c, off);
        }
        if (lane == 0) {
            g_part[blockIdx.x][0] = f;
            g_part[blockIdx.x][1] = p;
            g_part[blockIdx.x][2] = c;
        }
    }

    // ---- last-block finalize ----
    __shared__ bool s_is_last;
    __threadfence();                 // release: g_part writes visible chip-wide
    __syncthreads();
    if (threadIdx.x == 0) {
        unsigned int ticket = atomicAdd(&g_ticket, 1u);
        s_is_last = (ticket == (unsigned int)(gridDim.x - 1));
    }
    __syncthreads();
    if (!s_is_last) return;

    __threadfence();                 // acquire: see all blocks' partials

    double dfne = 0.0, dfpe = 0.0, dcnt = 0.0;
    for (int i = threadIdx.x; i < NBLK; i += NTHR) {
        dfne += (double)g_part[i][0];
        dfpe += (double)g_part[i][1];
        dcnt += (double)g_part[i][2];
    }
    #pragma unroll
    for (int off = 16; off > 0; off >>= 1) {
        dfne += __shfl_down_sync(0xFFFFFFFFu, dfne, off);
        dfpe += __shfl_down_sync(0xFFFFFFFFu, dfpe, off);
        dcnt += __shfl_down_sync(0xFFFFFFFFu, dcnt, off);
    }
    __shared__ double s_f[NTHR / 32], s_p[NTHR / 32], s_c[NTHR / 32];
    if (lane == 0) { s_f[wid] = dfne; s_p[wid] = dfpe; s_c[wid] = dcnt; }
    __syncthreads();
    if (threadIdx.x == 0) {
        double F = 0.0, P = 0.0, Cn = 0.0;
        #pragma unroll
        for (int w = 0; w < NTHR / 32; w++) { F += s_f[w]; P += s_p[w]; Cn += s_c[w]; }
        float fne_num = (float)Cn;
        float fpe_num = n_total - fne_num;
        out[0] = (float)(P / (double)fpe_num + F / (double)fne_num);
        __threadfence();
        g_ticket = 0;                // deterministic reset for next graph replay
    }
}

extern "C" void kernel_launch(void* const* d_in, const int* in_sizes, int n_in,
                              void* d_out, int out_size)
{
    const float4* preds  = (const float4*)d_in[0];
    const int4*   tgt4   = (const int4*)d_in[1];
    const int*    oi_ptr = (const int*)d_in[2];
    float*        out    = (float*)d_out;

    int n_rows  = in_sizes[0] / 4;     // B
    int n_quads = n_rows / 4;

    mfe_fused_kernel<<<NBLK, NTHR>>>(preds, tgt4, oi_ptr, n_quads, (float)n_rows, out);
}